// round 17
// baseline (speedup 1.0000x reference)
#include <cuda_runtime.h>
#include <cstddef>

// GazeLSTM on GB300 (sm_103a). B=16384, T=128, half=64.
// Kernel 1 (back_kernel, 64 thr / 32 b's): 2-warp scan of the backward chain.
//   w0: steps 0..31 direct (rows 0..31, leaves v31 in smem).
//   w1: running matrix products P_t for steps 32..63 (stored to smem);
//       after one __syncthreads, x_t = P_t * v31 -> rows 32..63. R read once.
// Kernel 2 (mix_kernel, 128 thr): blocks [0,nlstm) = R5's proven LSTM
//   (reads rows 0..63 from out, 65 steps, writes row 64); blocks [nlstm,..)
//   = 4 independent forward-chain warps (rows 65..127). LSTM overlaps fwd.

#define BT 32

__device__ __forceinline__ unsigned long long pk2(float lo, float hi) {
    unsigned long long r; asm("mov.b64 %0, {%1, %2};" : "=l"(r) : "f"(lo), "f"(hi)); return r;
}
__device__ __forceinline__ void upk2(float& lo, float& hi, unsigned long long v) {
    asm("mov.b64 {%0, %1}, %2;" : "=f"(lo), "=f"(hi) : "l"(v));
}
__device__ __forceinline__ unsigned long long fma2(unsigned long long a, unsigned long long b, unsigned long long c) {
    unsigned long long d; asm("fma.rn.f32x2 %0, %1, %2, %3;" : "=l"(d) : "l"(a), "l"(b), "l"(c)); return d;
}
__device__ __forceinline__ float tanhx(float x) {
    float y; asm("tanh.approx.f32 %0, %1;" : "=f"(y) : "f"(x)); return y;
}

#define CP16(dst_u32, src_ptr) \
    asm volatile("cp.async.cg.shared.global [%0], [%1], 16;" :: "r"(dst_u32), "l"(src_ptr))
#define CP_COMMIT() asm volatile("cp.async.commit_group;")
#define CP_WAIT1()  asm volatile("cp.async.wait_group 1;")
#define CP_WAIT0()  asm volatile("cp.async.wait_group 0;")

// Stage one C=4 chunk (32 b x 9 quads), 9 CP16/lane. j0 % 4 == 0 required.
__device__ __forceinline__ void stage4(float4* __restrict__ sdst,
                                       const float4* __restrict__ src4base,
                                       int t9q, int lane) {
    int bp = lane / 9, q = lane - bp * 9;
#pragma unroll
    for (int k = 0; k < 9; k++) {
        const float4* src = src4base + (size_t)bp * t9q + q;
        unsigned dst = (unsigned)__cvta_generic_to_shared(sdst + q * BT + (bp ^ q));
        CP16(dst, src);
        q += 5; bp += 3;                  // 32 = 3*9 + 5
        if (q >= 9) { q -= 9; bp += 1; }
    }
}

template <int M>
__device__ __forceinline__ void loadA4(float* A, const float4* __restrict__ buf, int lane) {
    constexpr int F0 = 9 * M, QA = F0 >> 2, OFF = F0 & 3;
    float tmp[12];
    *(float4*)(tmp + 0) = buf[(QA + 0) * BT + (lane ^ (QA + 0))];
    *(float4*)(tmp + 4) = buf[(QA + 1) * BT + (lane ^ (QA + 1))];
    *(float4*)(tmp + 8) = buf[(QA + 2) * BT + (lane ^ (QA + 2))];
#pragma unroll
    for (int i = 0; i < 9; i++) A[i] = tmp[OFF + i];
}

// Coalesced writeback: NF floats/b for 32 b's from swizzled sout.
template <int NF>
__device__ __forceinline__ void store_chain(float* __restrict__ gdst, size_t T3,
                                            const float* __restrict__ sout, int lane) {
    int bp = lane / NF, e = lane - bp * NF;
    constexpr int DB = BT / NF, DE = BT % NF;
#pragma unroll
    for (int k = 0; k < NF; k++) {
        gdst[(size_t)bp * T3 + e] = sout[e * BT + (bp ^ e)];
        bp += DB; e += DE;
        if (e >= NF) { e -= NF; bp += 1; }
    }
}

// ================= Kernel 1: backward scan =================
// dyn smem: [0,18432) staging (w*9216, two 4608 buffers each)
//           [18432,55296) P products, [55296,55808) v31,
//           [55808,57344) sout w0, [57344,60416) sout w1.
#define K1_SMEM 60416

__global__ __launch_bounds__(64) void back_kernel(
    const float* __restrict__ dir, const float* __restrict__ R,
    float* __restrict__ out, int B, int T)
{
    extern __shared__ char smem[];
    const int half = T >> 1;              // 64
    const int seg  = half >> 1;           // 32
    const int t9q = (T * 9) >> 2;
    const size_t T3 = (size_t)T * 3;
    const int tid = threadIdx.x;
    const int lane = tid & 31;
    const int w = tid >> 5;
    const int bbase = blockIdx.x * BT;
    const int nch = seg >> 2;             // 8

    const float4* R4 = (const float4*)R + (size_t)bbase * t9q;
    float* oblk = out + (size_t)bbase * T3;
    float4* buf0 = (float4*)(smem + w * 9216);
    float4* buf1 = buf0 + 288;
    float4* bufs[2] = { buf0, buf1 };
    float* P   = (float*)(smem + 18432);
    float* V31 = (float*)(smem + 55296);

    if (w == 0) {
        // ---- steps 0..31 direct: x_t = R[63-t]^T x_{t-1}, x_{-1} = dir ----
        float* so = (float*)(smem + 55808);
        float v0 = __ldg(dir + (size_t)(bbase + lane) * 3 + 0);
        float v1 = __ldg(dir + (size_t)(bbase + lane) * 3 + 1);
        float v2 = __ldg(dir + (size_t)(bbase + lane) * 3 + 2);

        stage4(bufs[0], R4 + (((half - 4) * 9) >> 2), t9q, lane); CP_COMMIT();
        for (int cc = 0; cc < nch; cc++) {
            if (cc + 1 < nch) {
                stage4(bufs[(cc + 1) & 1], R4 + (((half - 4 * (cc + 2)) * 9) >> 2), t9q, lane);
                CP_COMMIT(); CP_WAIT1();
            } else CP_WAIT0();
            __syncwarp();
            const float4* buf = bufs[cc & 1];
            int eo = 0;
#pragma unroll
            for (int k = 0; k < 4; k++) {
                float A[9];
                switch (k) {   // matrix slot 3-k (j descending within chunk)
                    case 0:  loadA4<3>(A, buf, lane); break;
                    case 1:  loadA4<2>(A, buf, lane); break;
                    case 2:  loadA4<1>(A, buf, lane); break;
                    default: loadA4<0>(A, buf, lane); break;
                }
                float n0 = fmaf(A[6], v2, fmaf(A[3], v1, A[0] * v0));
                float n1 = fmaf(A[7], v2, fmaf(A[4], v1, A[1] * v0));
                float n2 = fmaf(A[8], v2, fmaf(A[5], v1, A[2] * v0));
                v0 = n0; v1 = n1; v2 = n2;
                so[(eo + 0) * BT + (lane ^ (eo + 0))] = v0;
                so[(eo + 1) * BT + (lane ^ (eo + 1))] = v1;
                so[(eo + 2) * BT + (lane ^ (eo + 2))] = v2;
                eo += 3;
            }
            __syncwarp();
            store_chain<12>(oblk + (size_t)(4 * cc) * 3, T3, so, lane);
            __syncwarp();
        }
        V31[0 * BT + lane] = v0;
        V31[1 * BT + lane] = v1;
        V31[2 * BT + lane] = v2;
        __syncthreads();                   // publish v31 (P already written by w1)
    } else {
        // ---- products for steps 32..63: P_si = R[31-si]^T * P_{si-1} ----
        float M[9] = {1.f,0.f,0.f, 0.f,1.f,0.f, 0.f,0.f,1.f};
        stage4(bufs[0], R4 + (((seg - 4) * 9) >> 2), t9q, lane); CP_COMMIT();
        for (int cc = 0; cc < nch; cc++) {
            if (cc + 1 < nch) {
                stage4(bufs[(cc + 1) & 1], R4 + (((seg - 4 * (cc + 2)) * 9) >> 2), t9q, lane);
                CP_COMMIT(); CP_WAIT1();
            } else CP_WAIT0();
            __syncwarp();
            const float4* buf = bufs[cc & 1];
#pragma unroll
            for (int k = 0; k < 4; k++) {
                float A[9];
                switch (k) {
                    case 0:  loadA4<3>(A, buf, lane); break;
                    case 1:  loadA4<2>(A, buf, lane); break;
                    case 2:  loadA4<1>(A, buf, lane); break;
                    default: loadA4<0>(A, buf, lane); break;
                }
                float NM[9];
#pragma unroll
                for (int r = 0; r < 3; r++)
#pragma unroll
                    for (int c = 0; c < 3; c++)
                        NM[r*3+c] = fmaf(A[6+r], M[6+c], fmaf(A[3+r], M[3+c], A[r] * M[c]));
#pragma unroll
                for (int i = 0; i < 9; i++) M[i] = NM[i];
                const int si = 4 * cc + k;
#pragma unroll
                for (int e = 0; e < 9; e++) P[(si * 9 + e) * BT + lane] = M[e];
            }
        }
        __syncthreads();                   // wait for v31

        float* so = (float*)(smem + 57344);
        const float u0 = V31[0 * BT + lane];
        const float u1 = V31[1 * BT + lane];
        const float u2 = V31[2 * BT + lane];
        for (int g = 0; g < 4; g++) {
            int eo = 0;
#pragma unroll
            for (int k = 0; k < 8; k++) {
                const int si = 8 * g + k;
                float p[9];
#pragma unroll
                for (int e = 0; e < 9; e++) p[e] = P[(si * 9 + e) * BT + lane];
                float x0 = fmaf(p[2], u2, fmaf(p[1], u1, p[0] * u0));
                float x1 = fmaf(p[5], u2, fmaf(p[4], u1, p[3] * u0));
                float x2 = fmaf(p[8], u2, fmaf(p[7], u1, p[6] * u0));
                so[(eo + 0) * BT + (lane ^ (eo + 0))] = x0;
                so[(eo + 1) * BT + (lane ^ (eo + 1))] = x1;
                so[(eo + 2) * BT + (lane ^ (eo + 2))] = x2;
                eo += 3;
            }
            __syncwarp();
            store_chain<24>(oblk + (size_t)(seg + 8 * g) * 3, T3, so, lane);
            __syncwarp();
        }
    }
}

// ================= Kernel 2: LSTM blocks + forward blocks =================

#define LBT 128
#define LQ  6
#define LS  8

// R5's proven LSTM step (packed f32x2, prescaled weights).
#define LSTM_STEP(x0, x1, x2)                                                        \
    do {                                                                             \
        unsigned long long xx0 = pk2((x0), (x0)), xx1 = pk2((x1), (x1)), xx2 = pk2((x2), (x2)); \
        unsigned long long hh0 = pk2(h0, h0), hh1 = pk2(h1, h1), hh2 = pk2(h2, h2);  \
        float th[12];                                                                \
        _Pragma("unroll") for (int p = 0; p < 6; p++) {                              \
            unsigned long long xp = fma2(WI[p][0], xx0, fma2(WI[p][1], xx1, fma2(WI[p][2], xx2, BS[p]))); \
            unsigned long long g  = fma2(WH[p][0], hh0, fma2(WH[p][1], hh1, fma2(WH[p][2], hh2, xp)));    \
            float a_, b_; upk2(a_, b_, g);                                           \
            th[2*p] = tanhx(a_); th[2*p+1] = tanhx(b_);                              \
        }                                                                            \
        float i0 = fmaf(0.5f, th[0], 0.5f), i1 = fmaf(0.5f, th[1], 0.5f), i2 = fmaf(0.5f, th[2], 0.5f); \
        float f0 = fmaf(0.5f, th[3], 0.5f), f1 = fmaf(0.5f, th[4], 0.5f), f2 = fmaf(0.5f, th[5], 0.5f); \
        float o0 = fmaf(0.5f, th[9], 0.5f), o1 = fmaf(0.5f, th[10], 0.5f), o2 = fmaf(0.5f, th[11], 0.5f); \
        c0 = fmaf(f0, c0, i0 * th[6]);                                               \
        c1 = fmaf(f1, c1, i1 * th[7]);                                               \
        c2 = fmaf(f2, c2, i2 * th[8]);                                               \
        h0 = o0 * tanhx(c0); h1 = o1 * tanhx(c1); h2 = o2 * tanhx(c2);               \
    } while (0)

// Stage LSTM input chunk: 128 b's x LQ quads (R5-proven).
__device__ __forceinline__ void stage_chunkL(float4* __restrict__ sdst,
                                             const float4* __restrict__ src4base,
                                             int t3q, int tid) {
    int bp = tid / LQ, q = tid - bp * LQ;
#pragma unroll
    for (int k = 0; k < LQ; k++) {
        const float4* src = src4base + (size_t)bp * t3q + q;
        unsigned dst = (unsigned)__cvta_generic_to_shared(sdst + q * LBT + (bp ^ q));
        CP16(dst, src);
        q += 2; bp += 21;                 // 128 = 21*6 + 2
        if (q >= LQ) { q -= LQ; bp += 1; }
    }
}

__global__ __launch_bounds__(LBT) void mix_kernel(
    const float* __restrict__ dir, const float* __restrict__ R,
    const float* __restrict__ Wih, const float* __restrict__ Whh,
    const float* __restrict__ bih, const float* __restrict__ bhh,
    float* __restrict__ out, int B, int T, int nlstm)
{
    __shared__ char smem2[44032];

    const int half = T >> 1;
    const size_t T3 = (size_t)T * 3;
    const int tid = threadIdx.x;

    if ((int)blockIdx.x < nlstm) {
        // ============ LSTM block: 128 b's (R5 verbatim) ============
        float4* sbufL = (float4*)smem2;               // [2][LQ*LBT]
        const int t3q = (T * 3) >> 2;
        const int bbase = blockIdx.x * LBT;
        const int nchunks = half / LS;                // 8

        unsigned long long WI[6][3], WH[6][3], BS[6];
#pragma unroll
        for (int p = 0; p < 6; p++) {
            const int g0 = 2 * p, g1 = 2 * p + 1;
            const float s0 = (g0 >= 6 && g0 <= 8) ? 1.0f : 0.5f;
            const float s1 = (g1 >= 6 && g1 <= 8) ? 1.0f : 0.5f;
#pragma unroll
            for (int j = 0; j < 3; j++) {
                WI[p][j] = pk2(__ldg(Wih + g0*3 + j) * s0, __ldg(Wih + g1*3 + j) * s1);
                WH[p][j] = pk2(__ldg(Whh + g0*3 + j) * s0, __ldg(Whh + g1*3 + j) * s1);
            }
            BS[p] = pk2((__ldg(bih + g0) + __ldg(bhh + g0)) * s0,
                        (__ldg(bih + g1) + __ldg(bhh + g1)) * s1);
        }

        float h0 = 0.f, h1 = 0.f, h2 = 0.f, c0 = 0.f, c1 = 0.f, c2 = 0.f;
        const float4* O4 = (const float4*)out + (size_t)bbase * t3q;

        stage_chunkL(sbufL, O4, t3q, tid);
        CP_COMMIT();

        for (int cc = 0; cc < nchunks; cc++) {
            if (cc + 1 < nchunks) {
                stage_chunkL(sbufL + ((cc + 1) & 1) * (LQ * LBT), O4 + (cc + 1) * LQ, t3q, tid);
                CP_COMMIT(); CP_WAIT1();
            } else CP_WAIT0();
            __syncthreads();

            const float4* buf = sbufL + (cc & 1) * (LQ * LBT);
            float x[4 * LQ];
#pragma unroll
            for (int q = 0; q < LQ; q++)
                *(float4*)(x + 4 * q) = buf[q * LBT + (tid ^ q)];

#pragma unroll
            for (int s = 0; s < LS; s++)
                LSTM_STEP(x[3 * s + 0], x[3 * s + 1], x[3 * s + 2]);

            __syncthreads();
        }

        const float d0 = __ldg(dir + (size_t)(bbase + tid) * 3 + 0);
        const float d1 = __ldg(dir + (size_t)(bbase + tid) * 3 + 1);
        const float d2 = __ldg(dir + (size_t)(bbase + tid) * 3 + 2);
        LSTM_STEP(d0, d1, d2);

        float* ob = out + (size_t)(bbase + tid) * T3 + (size_t)half * 3;
        ob[0] = h0; ob[1] = h1; ob[2] = h2;
    } else {
        // ============ forward block: 4 independent warps x 32 b's ============
        const int lane = tid & 31;
        const int w = tid >> 5;
        const int t9q = (T * 9) >> 2;
        const int bbase = ((int)blockIdx.x - nlstm) * LBT + w * BT;
        const float4* R4 = (const float4*)R + (size_t)bbase * t9q;
        float* oblk = out + (size_t)bbase * T3;
        float4* buf0 = (float4*)(smem2 + w * 11008);
        float4* buf1 = buf0 + 288;
        float4* bufs[2] = { buf0, buf1 };
        float* so = (float*)(smem2 + w * 11008 + 9216);
        const int nsteps = T - 1 - half;              // 63
        const int nchunks = 16;

        float v0 = __ldg(dir + (size_t)(bbase + lane) * 3 + 0);
        float v1 = __ldg(dir + (size_t)(bbase + lane) * 3 + 1);
        float v2 = __ldg(dir + (size_t)(bbase + lane) * 3 + 2);

        stage4(bufs[0], R4 + ((half * 9) >> 2), t9q, lane); CP_COMMIT();
        for (int cc = 0; cc < nchunks; cc++) {
            if (cc + 1 < nchunks) {
                stage4(bufs[(cc + 1) & 1], R4 + (((half + 4 * (cc + 1)) * 9) >> 2), t9q, lane);
                CP_COMMIT(); CP_WAIT1();
            } else CP_WAIT0();
            __syncwarp();

            const float4* buf = bufs[cc & 1];
            const int ns = (nsteps - 4 * cc) < 4 ? (nsteps - 4 * cc) : 4;
#pragma unroll
            for (int sub = 0; sub < 4; sub++) {
                if (sub < ns) {
                    float A[9];
                    switch (sub) {
                        case 0:  loadA4<0>(A, buf, lane); break;
                        case 1:  loadA4<1>(A, buf, lane); break;
                        case 2:  loadA4<2>(A, buf, lane); break;
                        default: loadA4<3>(A, buf, lane); break;
                    }
                    float n0 = fmaf(A[2], v2, fmaf(A[1], v1, A[0] * v0));
                    float n1 = fmaf(A[5], v2, fmaf(A[4], v1, A[3] * v0));
                    float n2 = fmaf(A[8], v2, fmaf(A[7], v1, A[6] * v0));
                    v0 = n0; v1 = n1; v2 = n2;
                    const int eo = 3 * sub;
                    so[(eo + 0) * BT + (lane ^ (eo + 0))] = v0;
                    so[(eo + 1) * BT + (lane ^ (eo + 1))] = v1;
                    so[(eo + 2) * BT + (lane ^ (eo + 2))] = v2;
                }
            }
            __syncwarp();
            float* gdst = oblk + (size_t)(half + 1 + 4 * cc) * 3;
            if (ns == 4) store_chain<12>(gdst, T3, so, lane);
            else         store_chain<9>(gdst, T3, so, lane);
            __syncwarp();
        }
    }
}

// ---------------- launch ----------------

extern "C" void kernel_launch(void* const* d_in, const int* in_sizes, int n_in,
                              void* d_out, int out_size)
{
    const float* dir = (const float*)d_in[0];
    const float* R   = (const float*)d_in[1];
    const float* Wih = (const float*)d_in[2];
    const float* Whh = (const float*)d_in[3];
    const float* bih = (const float*)d_in[4];
    const float* bhh = (const float*)d_in[5];
    float* out = (float*)d_out;

    const int B = in_sizes[0] / 3;
    const int T = in_sizes[1] / (B * 9);
    const int nlstm = B / LBT;   // 128
    const int nfwd  = B / LBT;   // 128

    static int attr_set = 0;
    if (!attr_set) {
        cudaFuncSetAttribute(back_kernel, cudaFuncAttributeMaxDynamicSharedMemorySize, K1_SMEM);
        attr_set = 1;
    }

    back_kernel<<<B / BT, 64, K1_SMEM>>>(dir, R, out, B, T);
    mix_kernel<<<nlstm + nfwd, LBT>>>(dir, R, Wih, Whh, bih, bhh, out, B, T, nlstm);
}